// round 1
// baseline (speedup 1.0000x reference)
#include <cuda_runtime.h>

#define TSTEPS   64
#define HID      64
#define SEQ_TILE 32
#define NTILES   300      // 9600 / 32
#define NTHREADS 256
#define HP       36       // padded row stride (floats) for h buffers
#define NBLOCKS  148
#define BN_TOTAL 9600

__device__ __forceinline__ float sigf(float x) {
    return __fdividef(1.0f, 1.0f + __expf(-x));
}
__device__ __forceinline__ float tanh_fast(float x) {
    return __fdividef(2.0f, 1.0f + __expf(-2.0f * x)) - 1.0f;
}

__global__ void __launch_bounds__(NTHREADS, 1)
lstm_kernel(const float* __restrict__ x,
            const float* __restrict__ Wih0, const float* __restrict__ Whh0,
            const float* __restrict__ bih0, const float* __restrict__ bhh0,
            const float* __restrict__ Wih1, const float* __restrict__ Whh1,
            const float* __restrict__ bih1, const float* __restrict__ bhh1,
            const float* __restrict__ fc1_w, const float* __restrict__ fc1_b,
            const float* __restrict__ fc2_w, const float* __restrict__ fc2_b,
            float* __restrict__ out)
{
    extern __shared__ float sm[];
    float* sW0 = sm;                    // [64][256]  Whh0^T  (k-major, unit*4+gate)
    float* sW1 = sW0 + 16384;           // Wih1^T
    float* sW2 = sW1 + 16384;           // Whh1^T
    float* sH0 = sW2 + 16384;           // [64][HP]   h0 transposed [k][seq]
    float* sH1 = sH0 + 64 * HP;         // [64][HP]
    float* sX  = sH1 + 64 * HP;         // [64][32]   x transposed [t][seq]

    const int tid   = threadIdx.x;
    const int j     = tid & 63;         // hidden unit owned by this thread
    const int oct   = tid >> 6;         // which group of 8 sequences
    const int sbase = oct * 8;

    // One-time weight transpose into smem: dst[k*256 + j*4 + g] = W[(g*64+j)*64 + k]
    for (int idx = tid; idx < 16384; idx += NTHREADS) {
        int k = idx >> 8;
        int r = idx & 255;
        int jj = r >> 2, g = r & 3;
        int src = (g * 64 + jj) * 64 + k;
        sW0[idx] = Whh0[src];
        sW1[idx] = Wih1[src];
        sW2[idx] = Whh1[src];
    }

    // Per-thread constants (per unit j, gates i,f,g,o)
    float wx0[4], b0v[4], b1v[4];
#pragma unroll
    for (int g = 0; g < 4; g++) {
        int row = g * 64 + j;
        wx0[g] = Wih0[row];
        b0v[g] = bih0[row] + bhh0[row];
        b1v[g] = bih1[row] + bhh1[row];
    }

    for (int tile = blockIdx.x; tile < NTILES; tile += gridDim.x) {
        const int n0 = tile * SEQ_TILE;
        __syncthreads();   // previous tile's readers done before we overwrite smem

        // Stage x tile: sX[t][s] = x[(n0+s)*64 + t]
        for (int idx = tid; idx < TSTEPS * SEQ_TILE; idx += NTHREADS) {
            int t = idx >> 5, s = idx & 31;
            sX[t * 32 + s] = x[(n0 + s) * TSTEPS + t];
        }
        for (int idx = tid; idx < 64 * HP; idx += NTHREADS) {
            sH0[idx] = 0.0f;
            sH1[idx] = 0.0f;
        }
        float c0[8], c1[8];
#pragma unroll
        for (int s = 0; s < 8; s++) { c0[s] = 0.0f; c1[s] = 0.0f; }
        __syncthreads();

        for (int t = 0; t < TSTEPS; t++) {
            // ---------------- layer 0 ----------------
            float a[4][8];
            {
                const float4 xA = *(const float4*)&sX[t * 32 + sbase];
                const float4 xB = *(const float4*)&sX[t * 32 + sbase + 4];
                const float xv[8] = {xA.x, xA.y, xA.z, xA.w, xB.x, xB.y, xB.z, xB.w};
#pragma unroll
                for (int g = 0; g < 4; g++)
#pragma unroll
                    for (int s = 0; s < 8; s++)
                        a[g][s] = fmaf(wx0[g], xv[s], b0v[g]);
            }
#pragma unroll 4
            for (int k = 0; k < HID; k++) {
                const float4 w  = *(const float4*)&sW0[k * 256 + j * 4];
                const float4 hA = *(const float4*)&sH0[k * HP + sbase];
                const float4 hB = *(const float4*)&sH0[k * HP + sbase + 4];
                const float wv[4] = {w.x, w.y, w.z, w.w};
                const float hv[8] = {hA.x, hA.y, hA.z, hA.w, hB.x, hB.y, hB.z, hB.w};
#pragma unroll
                for (int g = 0; g < 4; g++)
#pragma unroll
                    for (int s = 0; s < 8; s++)
                        a[g][s] = fmaf(wv[g], hv[s], a[g][s]);
            }
            float h0n[8];
#pragma unroll
            for (int s = 0; s < 8; s++) {
                float ig = sigf(a[0][s]);
                float fg = sigf(a[1][s]);
                float gg = tanh_fast(a[2][s]);
                float og = sigf(a[3][s]);
                c0[s]  = fmaf(fg, c0[s], ig * gg);
                h0n[s] = og * tanh_fast(c0[s]);
            }
            __syncthreads();   // all reads of old sH0 done
            *(float4*)&sH0[j * HP + sbase]     = make_float4(h0n[0], h0n[1], h0n[2], h0n[3]);
            *(float4*)&sH0[j * HP + sbase + 4] = make_float4(h0n[4], h0n[5], h0n[6], h0n[7]);
            __syncthreads();   // new h0 visible

            // ---------------- layer 1 ----------------
#pragma unroll
            for (int g = 0; g < 4; g++)
#pragma unroll
                for (int s = 0; s < 8; s++)
                    a[g][s] = b1v[g];
#pragma unroll 2
            for (int k = 0; k < HID; k++) {
                const float4 w1 = *(const float4*)&sW1[k * 256 + j * 4];
                const float4 w2 = *(const float4*)&sW2[k * 256 + j * 4];
                const float4 p0 = *(const float4*)&sH0[k * HP + sbase];
                const float4 p1 = *(const float4*)&sH0[k * HP + sbase + 4];
                const float4 q0 = *(const float4*)&sH1[k * HP + sbase];
                const float4 q1 = *(const float4*)&sH1[k * HP + sbase + 4];
                const float w1v[4] = {w1.x, w1.y, w1.z, w1.w};
                const float w2v[4] = {w2.x, w2.y, w2.z, w2.w};
                const float h0v[8] = {p0.x, p0.y, p0.z, p0.w, p1.x, p1.y, p1.z, p1.w};
                const float h1v[8] = {q0.x, q0.y, q0.z, q0.w, q1.x, q1.y, q1.z, q1.w};
#pragma unroll
                for (int g = 0; g < 4; g++)
#pragma unroll
                    for (int s = 0; s < 8; s++)
                        a[g][s] = fmaf(w1v[g], h0v[s], a[g][s]);
#pragma unroll
                for (int g = 0; g < 4; g++)
#pragma unroll
                    for (int s = 0; s < 8; s++)
                        a[g][s] = fmaf(w2v[g], h1v[s], a[g][s]);
            }
            float h1n[8];
#pragma unroll
            for (int s = 0; s < 8; s++) {
                float ig = sigf(a[0][s]);
                float fg = sigf(a[1][s]);
                float gg = tanh_fast(a[2][s]);
                float og = sigf(a[3][s]);
                c1[s]  = fmaf(fg, c1[s], ig * gg);
                h1n[s] = og * tanh_fast(c1[s]);
            }
            __syncthreads();
            *(float4*)&sH1[j * HP + sbase]     = make_float4(h1n[0], h1n[1], h1n[2], h1n[3]);
            *(float4*)&sH1[j * HP + sbase + 4] = make_float4(h1n[4], h1n[5], h1n[6], h1n[7]);
            __syncthreads();
        }

        // ---- outputs: hT = h1 final ----
        for (int idx = tid; idx < SEQ_TILE * HID; idx += NTHREADS) {
            int s = idx >> 6, k = idx & 63;
            out[(n0 + s) * HID + k] = sH1[k * HP + s];
        }
        // ---- FC head: one thread per sequence ----
        if (tid < SEQ_TILE) {
            const int s = tid;
            const float xl = sX[(TSTEPS - 1) * 32 + s];
            float acc = fc2_b[0];
#pragma unroll 1
            for (int u = 0; u < 16; u++) {
                float a1 = fc1_b[u];
#pragma unroll 4
                for (int k = 0; k < HID; k++)
                    a1 = fmaf(fc1_w[u * 65 + k], sH1[k * HP + s], a1);
                a1 = fmaf(fc1_w[u * 65 + 64], xl, a1);
                a1 = fmaxf(a1, 0.0f);
                acc = fmaf(fc2_w[u], a1, acc);
            }
            out[BN_TOTAL * HID + n0 + s] = acc;
        }
        // next tile's leading __syncthreads() protects sX/sH reuse
    }
}

extern "C" void kernel_launch(void* const* d_in, const int* in_sizes, int n_in,
                              void* d_out, int out_size) {
    (void)in_sizes; (void)n_in; (void)out_size;
    const size_t smem = (size_t)(3 * 16384 + 2 * 64 * HP + 64 * 32) * sizeof(float);
    cudaFuncSetAttribute(lstm_kernel, cudaFuncAttributeMaxDynamicSharedMemorySize, (int)smem);
    lstm_kernel<<<NBLOCKS, NTHREADS, smem>>>(
        (const float*)d_in[0],  (const float*)d_in[1],  (const float*)d_in[2],
        (const float*)d_in[3],  (const float*)d_in[4],  (const float*)d_in[5],
        (const float*)d_in[6],  (const float*)d_in[7],  (const float*)d_in[8],
        (const float*)d_in[9],  (const float*)d_in[10], (const float*)d_in[11],
        (const float*)d_in[12], (float*)d_out);
}

// round 2
// speedup vs baseline: 1.1455x; 1.1455x over previous
#include <cuda_runtime.h>

#define HID      64
#define TSTEPS   64
#define SEQ_TILE 32
#define NTILES   300
#define NTHREADS 256
#define HP       36
#define HSZ      (64 * HP)
#define NBLOCKS  148
#define BN_TOTAL 9600

typedef unsigned long long u64;

__device__ __forceinline__ u64 ffma2(u64 a, u64 b, u64 c) {
    u64 d;
    asm("fma.rn.f32x2 %0, %1, %2, %3;" : "=l"(d) : "l"(a), "l"(b), "l"(c));
    return d;
}
__device__ __forceinline__ u64 dup2(float w) {
    unsigned int wi = __float_as_uint(w);
    u64 r;
    asm("mov.b64 %0, {%1, %1};" : "=l"(r) : "r"(wi));
    return r;
}
__device__ __forceinline__ u64 pack2(float lo, float hi) {
    u64 r;
    asm("mov.b64 %0, {%1, %2};" : "=l"(r) : "r"(__float_as_uint(lo)), "r"(__float_as_uint(hi)));
    return r;
}
__device__ __forceinline__ float2 unpack2(u64 v) {
    unsigned int lo, hi;
    asm("mov.b64 {%0, %1}, %2;" : "=r"(lo), "=r"(hi) : "l"(v));
    return make_float2(__uint_as_float(lo), __uint_as_float(hi));
}
__device__ __forceinline__ float sigf(float x) {
    return __fdividef(1.0f, 1.0f + __expf(-x));
}
__device__ __forceinline__ float tanh_fast(float x) {
    return __fdividef(2.0f, 1.0f + __expf(-2.0f * x)) - 1.0f;
}

__global__ void __launch_bounds__(NTHREADS, 1)
lstm_kernel(const float* __restrict__ x,
            const float* __restrict__ Wih0, const float* __restrict__ Whh0,
            const float* __restrict__ bih0, const float* __restrict__ bhh0,
            const float* __restrict__ Wih1, const float* __restrict__ Whh1,
            const float* __restrict__ bih1, const float* __restrict__ bhh1,
            const float* __restrict__ fc1_w, const float* __restrict__ fc1_b,
            const float* __restrict__ fc2_w, const float* __restrict__ fc2_b,
            float* __restrict__ out)
{
    extern __shared__ float sm[];
    float* sW0 = sm;                    // [64][256]  Whh0^T  (k-major, j*4+g)
    float* sW1 = sW0 + 16384;           // Wih1^T
    float* sW2 = sW1 + 16384;           // Whh1^T
    float* sH0 = sW2 + 16384;           // [2][64][HP]  ping-pong h0, [k][seq]
    float* sH1 = sH0 + 2 * HSZ;         // [64][HP]     h1 (single buffer)

    const int tid   = threadIdx.x;
    const int j     = tid & 63;
    const int oct   = tid >> 6;
    const int sbase = oct * 8;

    // One-time weight transpose: dst[k*256 + j*4 + g] = W[(g*64+j)*64 + k]
    for (int idx = tid; idx < 16384; idx += NTHREADS) {
        int k = idx >> 8;
        int r = idx & 255;
        int jj = r >> 2, g = r & 3;
        int src = (g * 64 + jj) * 64 + k;
        sW0[idx] = Whh0[src];
        sW1[idx] = Wih1[src];
        sW2[idx] = Whh1[src];
    }

    // Per-thread constants (unit j, gates i,f,g,o) as packed duplicates
    u64 wx0d[4], b0d[4], b1d[4];
#pragma unroll
    for (int g = 0; g < 4; g++) {
        int row = g * 64 + j;
        wx0d[g] = dup2(Wih0[row]);
        b0d[g]  = dup2(bih0[row] + bhh0[row]);
        b1d[g]  = dup2(bih1[row] + bhh1[row]);
    }

    for (int tile = blockIdx.x; tile < NTILES; tile += gridDim.x) {
        const int n0 = tile * SEQ_TILE;
        __syncthreads();   // previous tile's smem readers done

        // zero the t=0 read buffers
        for (int idx = tid; idx < HSZ; idx += NTHREADS) {
            sH0[idx] = 0.0f;   // buffer p=0
            sH1[idx] = 0.0f;
        }
        float c0[8], c1[8];
#pragma unroll
        for (int s = 0; s < 8; s++) { c0[s] = 0.0f; c1[s] = 0.0f; }

        const float* xb = x + (size_t)(n0 + sbase) * TSTEPS;
        __syncthreads();

        for (int t = 0; t < TSTEPS; t++) {
            const int p = t & 1;
            const float* h0r = sH0 + p * HSZ;
            float*       h0w = sH0 + (p ^ 1) * HSZ;

            // issue x loads early; consumed after the k-loop
            float xv[8];
#pragma unroll
            for (int i = 0; i < 8; i++) xv[i] = xb[i * TSTEPS + t];

            // ---------------- layer 0 ----------------
            u64 a[4][4];
#pragma unroll
            for (int g = 0; g < 4; g++)
#pragma unroll
                for (int q = 0; q < 4; q++) a[g][q] = b0d[g];

#pragma unroll 4
            for (int k = 0; k < HID; k++) {
                const float4 w = *(const float4*)&sW0[k * 256 + (j << 2)];
                const ulonglong2 hA = *(const ulonglong2*)&h0r[k * HP + sbase];
                const ulonglong2 hB = *(const ulonglong2*)&h0r[k * HP + sbase + 4];
                const u64 hp[4] = {hA.x, hA.y, hB.x, hB.y};
                const u64 wd[4] = {dup2(w.x), dup2(w.y), dup2(w.z), dup2(w.w)};
#pragma unroll
                for (int g = 0; g < 4; g++)
#pragma unroll
                    for (int q = 0; q < 4; q++)
                        a[g][q] = ffma2(wd[g], hp[q], a[g][q]);
            }
            {
                const u64 xp[4] = {pack2(xv[0], xv[1]), pack2(xv[2], xv[3]),
                                   pack2(xv[4], xv[5]), pack2(xv[6], xv[7])};
#pragma unroll
                for (int g = 0; g < 4; g++)
#pragma unroll
                    for (int q = 0; q < 4; q++)
                        a[g][q] = ffma2(wx0d[g], xp[q], a[g][q]);
            }

            float h0n[8];
#pragma unroll
            for (int q = 0; q < 4; q++) {
                float2 iv = unpack2(a[0][q]);
                float2 fv = unpack2(a[1][q]);
                float2 gv = unpack2(a[2][q]);
                float2 ov = unpack2(a[3][q]);
                float ig0 = sigf(iv.x), ig1 = sigf(iv.y);
                float fg0 = sigf(fv.x), fg1 = sigf(fv.y);
                float gg0 = tanh_fast(gv.x), gg1 = tanh_fast(gv.y);
                float og0 = sigf(ov.x), og1 = sigf(ov.y);
                c0[2*q]   = fmaf(fg0, c0[2*q],   ig0 * gg0);
                c0[2*q+1] = fmaf(fg1, c0[2*q+1], ig1 * gg1);
                h0n[2*q]   = og0 * tanh_fast(c0[2*q]);
                h0n[2*q+1] = og1 * tanh_fast(c0[2*q+1]);
            }
            *(float4*)&h0w[j * HP + sbase]     = make_float4(h0n[0], h0n[1], h0n[2], h0n[3]);
            *(float4*)&h0w[j * HP + sbase + 4] = make_float4(h0n[4], h0n[5], h0n[6], h0n[7]);
            __syncthreads();   // h0(new) visible for layer 1

            // ---------------- layer 1 ----------------
#pragma unroll
            for (int g = 0; g < 4; g++)
#pragma unroll
                for (int q = 0; q < 4; q++) a[g][q] = b1d[g];

#pragma unroll 2
            for (int k = 0; k < HID; k++) {
                const float4 w1 = *(const float4*)&sW1[k * 256 + (j << 2)];
                const float4 w2 = *(const float4*)&sW2[k * 256 + (j << 2)];
                const ulonglong2 pA = *(const ulonglong2*)&h0w[k * HP + sbase];
                const ulonglong2 pB = *(const ulonglong2*)&h0w[k * HP + sbase + 4];
                const ulonglong2 qA = *(const ulonglong2*)&sH1[k * HP + sbase];
                const ulonglong2 qB = *(const ulonglong2*)&sH1[k * HP + sbase + 4];
                const u64 h0p[4] = {pA.x, pA.y, pB.x, pB.y};
                const u64 h1p[4] = {qA.x, qA.y, qB.x, qB.y};
                const u64 w1d[4] = {dup2(w1.x), dup2(w1.y), dup2(w1.z), dup2(w1.w)};
                const u64 w2d[4] = {dup2(w2.x), dup2(w2.y), dup2(w2.z), dup2(w2.w)};
#pragma unroll
                for (int g = 0; g < 4; g++)
#pragma unroll
                    for (int q = 0; q < 4; q++)
                        a[g][q] = ffma2(w1d[g], h0p[q], a[g][q]);
#pragma unroll
                for (int g = 0; g < 4; g++)
#pragma unroll
                    for (int q = 0; q < 4; q++)
                        a[g][q] = ffma2(w2d[g], h1p[q], a[g][q]);
            }

            float h1n[8];
#pragma unroll
            for (int q = 0; q < 4; q++) {
                float2 iv = unpack2(a[0][q]);
                float2 fv = unpack2(a[1][q]);
                float2 gv = unpack2(a[2][q]);
                float2 ov = unpack2(a[3][q]);
                float ig0 = sigf(iv.x), ig1 = sigf(iv.y);
                float fg0 = sigf(fv.x), fg1 = sigf(fv.y);
                float gg0 = tanh_fast(gv.x), gg1 = tanh_fast(gv.y);
                float og0 = sigf(ov.x), og1 = sigf(ov.y);
                c1[2*q]   = fmaf(fg0, c1[2*q],   ig0 * gg0);
                c1[2*q+1] = fmaf(fg1, c1[2*q+1], ig1 * gg1);
                h1n[2*q]   = og0 * tanh_fast(c1[2*q]);
                h1n[2*q+1] = og1 * tanh_fast(c1[2*q+1]);
            }
            __syncthreads();   // all layer-1 reads of old sH1 done
            *(float4*)&sH1[j * HP + sbase]     = make_float4(h1n[0], h1n[1], h1n[2], h1n[3]);
            *(float4*)&sH1[j * HP + sbase + 4] = make_float4(h1n[4], h1n[5], h1n[6], h1n[7]);
        }
        __syncthreads();   // final sH1 writes visible

        // ---- hT output ----
        for (int idx = tid; idx < SEQ_TILE * HID; idx += NTHREADS) {
            int s = idx >> 6, k = idx & 63;
            out[(n0 + s) * HID + k] = sH1[k * HP + s];
        }
        // ---- FC head ----
        if (tid < SEQ_TILE) {
            const int s = tid;
            const float xl = x[(size_t)(n0 + s) * TSTEPS + (TSTEPS - 1)];
            float acc = fc2_b[0];
#pragma unroll 1
            for (int u = 0; u < 16; u++) {
                float a1 = fc1_b[u];
#pragma unroll 4
                for (int k = 0; k < HID; k++)
                    a1 = fmaf(fc1_w[u * 65 + k], sH1[k * HP + s], a1);
                a1 = fmaf(fc1_w[u * 65 + 64], xl, a1);
                a1 = fmaxf(a1, 0.0f);
                acc = fmaf(fc2_w[u], a1, acc);
            }
            out[BN_TOTAL * HID + n0 + s] = acc;
        }
    }
}

extern "C" void kernel_launch(void* const* d_in, const int* in_sizes, int n_in,
                              void* d_out, int out_size) {
    (void)in_sizes; (void)n_in; (void)out_size;
    const size_t smem = (size_t)(3 * 16384 + 3 * HSZ) * sizeof(float);
    cudaFuncSetAttribute(lstm_kernel, cudaFuncAttributeMaxDynamicSharedMemorySize, (int)smem);
    lstm_kernel<<<NBLOCKS, NTHREADS, smem>>>(
        (const float*)d_in[0],  (const float*)d_in[1],  (const float*)d_in[2],
        (const float*)d_in[3],  (const float*)d_in[4],  (const float*)d_in[5],
        (const float*)d_in[6],  (const float*)d_in[7],  (const float*)d_in[8],
        (const float*)d_in[9],  (const float*)d_in[10], (const float*)d_in[11],
        (const float*)d_in[12], (float*)d_out);
}